// round 15
// baseline (speedup 1.0000x reference)
#include <cuda_runtime.h>
#include <cuda_fp16.h>
#include <cstdint>

#define NFEAT   256
#define NHID    128
#define NCLS    16
#define MAXN    100000
#define MAXE    1600000
#define SCANB   1024
#define MAXBLK  128

// ---------------- scratch (device globals; no allocation allowed) ----------
__device__ int    g_cnt[MAXN];
__device__ int    g_cur[MAXN];
__device__ int    g_off[MAXN + 1];
__device__ int    g_bsum[MAXBLK];
__device__ int    g_done;
__device__ float  g_dinv[MAXN];
__device__ int2   g_edge[MAXE];             // x = src node, y = weight bits
__device__ uint32_t g_w1p[NHID * (NFEAT / 2)]; // W1 fp16, [n][k-pair] packed
__device__ __half g_h1h[(size_t)MAXN * NHID];   // h1 in fp16 (gather-friendly)
__device__ uint2  g_g1h[(size_t)MAXN * 32];     // g1 in fp16 (packed 4/lane)
__device__ __half g_h2h[(size_t)MAXN * NCLS];   // h2 in fp16
__device__ int    g_is64;

// ---------------- static host context: fork-join stream + events -----------
struct HxCtx {
    cudaStream_t s2;
    cudaEvent_t  evA, evB;
    bool ok;
    HxCtx() : ok(false) {
        if (cudaStreamCreateWithFlags(&s2, cudaStreamNonBlocking) != cudaSuccess) return;
        if (cudaEventCreateWithFlags(&evA, cudaEventDisableTiming) != cudaSuccess) return;
        if (cudaEventCreateWithFlags(&evB, cudaEventDisableTiming) != cudaSuccess) return;
        ok = true;
    }
};
static HxCtx g_hx;

// ---------------- index fetch (runtime int32/int64 dispatch) ---------------
__device__ __forceinline__ int edge_idx(const void* ei, long long pos, int is64) {
    if (is64) return (int)((const long long*)ei)[pos];
    return ((const int*)ei)[pos];
}

// ---------------- init: detect index dtype (zeroing moved to k_scan) -------
__global__ void k_init(const int* __restrict__ ei32, int E) {
    int samples = 4096;
    if (samples > E / 2) samples = E / 2;
    int nz = 0;
    for (int s = threadIdx.x; s < samples; s += blockDim.x)
        if (ei32[2 * s + 1] != 0) nz = 1;
    nz = __syncthreads_or(nz);
    if (threadIdx.x == 0) g_is64 = nz ? 0 : 1;
}

// ---------------- degree count (+ reset scan's done counter) ---------------
__global__ void k_count(const void* __restrict__ ei, int E) {
    if (blockIdx.x == 0 && threadIdx.x == 0) g_done = 0;
    int e = blockIdx.x * blockDim.x + threadIdx.x;
    if (e >= E) return;
    int c = edge_idx(ei, (long long)E + e, g_is64);
    atomicAdd(&g_cnt[c], 1);
}

// ---------------- single-pass scan: off/cur/dinv + zero cnt ----------------
// All nb (<=98) blocks are co-resident (one wave on 148 SMs), so the
// publish-then-spin pattern cannot deadlock.
__global__ void __launch_bounds__(SCANB) k_scan(int n, int nb) {
    __shared__ int warp_sums[32];
    __shared__ int s_prefix;
    int tid = threadIdx.x, lane = tid & 31, wid = tid >> 5;
    int b = blockIdx.x;
    int i = b * SCANB + tid;
    int v = (i < n) ? g_cnt[i] : 0;
    if (i < n) {
        g_dinv[i] = rsqrtf((float)v + 1.0f); // +1 = self loop
        g_cnt[i] = 0;                        // re-zero for next replay
    }
    int x = v;
    #pragma unroll
    for (int d = 1; d < 32; d <<= 1) {
        int y = __shfl_up_sync(0xffffffffu, x, d);
        if (lane >= d) x += y;
    }
    if (lane == 31) warp_sums[wid] = x;
    __syncthreads();
    if (wid == 0) {
        int s = warp_sums[lane];
        #pragma unroll
        for (int d = 1; d < 32; d <<= 1) {
            int y = __shfl_up_sync(0xffffffffu, s, d);
            if (lane >= d) s += y;
        }
        warp_sums[lane] = s;
    }
    __syncthreads();
    int excl = x - v + (wid ? warp_sums[wid - 1] : 0);
    int total = warp_sums[31];

    if (tid == 0) {
        g_bsum[b] = total;
        __threadfence();
        atomicAdd(&g_done, 1);
        while (*(volatile int*)&g_done < nb) { }
        __threadfence();
        int pre = 0;
        for (int j = 0; j < b; j++) pre += g_bsum[j];
        s_prefix = pre;
        if (b == nb - 1) g_off[n] = pre + total;
    }
    __syncthreads();
    int off = excl + s_prefix;
    if (i < n) { g_off[i] = off; g_cur[i] = off; }
}

// ---------------- scatter edges into CSC (interleaved src+w) ---------------
__global__ void k_scatter(const void* __restrict__ ei, int E) {
    int e = blockIdx.x * blockDim.x + threadIdx.x;
    if (e >= E) return;
    int is64 = g_is64;
    int r = edge_idx(ei, e, is64);
    int c = edge_idx(ei, (long long)E + e, is64);
    int p = atomicAdd(&g_cur[c], 1);
    g_edge[p] = make_int2(r, __float_as_int(g_dinv[r] * g_dinv[c]));
}

// ---------------- fp16 mma / ldmatrix helpers -------------------------------
__device__ __forceinline__ void mma_f16(float* d, const uint32_t* a, uint32_t b0, uint32_t b1) {
    asm("mma.sync.aligned.m16n8k16.row.col.f32.f16.f16.f32 "
        "{%0,%1,%2,%3}, {%4,%5,%6,%7}, {%8,%9}, {%0,%1,%2,%3};"
        : "+f"(d[0]), "+f"(d[1]), "+f"(d[2]), "+f"(d[3])
        : "r"(a[0]), "r"(a[1]), "r"(a[2]), "r"(a[3]), "r"(b0), "r"(b1));
}
__device__ __forceinline__ void ldmat4(uint32_t* r, uint32_t addr) {
    asm volatile("ldmatrix.sync.aligned.m8n8.x4.shared.b16 {%0,%1,%2,%3}, [%4];"
        : "=r"(r[0]), "=r"(r[1]), "=r"(r[2]), "=r"(r[3]) : "r"(addr));
}
__device__ __forceinline__ uint32_t pack_h2(float lo, float hi) {
    __half2 h = __floats2half2_rn(lo, hi);
    return *reinterpret_cast<uint32_t*>(&h);
}

// ---------------- W1 pre-convert: g_w1p[n][u] = (h(W1[2u][n]), h(W1[2u+1][n]))
__global__ void k_w1h(const float* __restrict__ W1) {
    int idx = blockIdx.x * blockDim.x + threadIdx.x;  // 0..16383
    int nn = idx >> 7, u = idx & 127;
    g_w1p[nn * 128 + u] = pack_h2(W1[(2 * u) * NHID + nn], W1[(2 * u + 1) * NHID + nn]);
}

// ---------------- GEMM1: 512 threads, 16 warps (4x4), warp tile 32x32 -------
#define AP2 12   // padded row length (uints)
#define BUFB (128 * AP2 * 4)   // bytes per buffer
__global__ void __launch_bounds__(512, 2) k_gemm1(const float* __restrict__ A,
                                                  int M) {
    __shared__ uint32_t As2[2][128][AP2];  // A halves: [buf][row][k-pair]
    __shared__ uint32_t Bs2[2][128][AP2];  // B halves: [buf][col][k-pair]
    const int tid    = threadIdx.x;
    const int lane   = tid & 31;
    const int wid    = tid >> 5;          // 0..15
    const int warp_m = (wid & 3) * 32;    // 4 warps along M
    const int warp_n = (wid >> 2) * 32;   // 4 warps along N
    const int brow   = blockIdx.x * 128;

    float acc[2][4][4];
    #pragma unroll
    for (int mt = 0; mt < 2; mt++)
        #pragma unroll
        for (int nt = 0; nt < 4; nt++)
            #pragma unroll
            for (int q = 0; q < 4; q++) acc[mt][nt][q] = 0.f;

    const int a_row = tid >> 2;          // 0..127
    const int a_kq  = (tid & 3) * 2;     // uint index 0,2,4,6
    const int b_nn  = a_row;
    const int b_kq  = a_kq;

    uint32_t addrA0[2], addrB0[2];
    #pragma unroll
    for (int mt = 0; mt < 2; mt++) {
        int row = warp_m + mt * 16 + (lane & 15);
        int c   = (lane >> 4) * 4;
        addrA0[mt] = (uint32_t)__cvta_generic_to_shared(&As2[0][row][c]);
    }
    #pragma unroll
    for (int i = 0; i < 2; i++) {
        int m = lane >> 3, r = lane & 7;
        int col = warp_n + (2 * i + (m >> 1)) * 8 + r;
        int c   = (m & 1) * 4;
        addrB0[i] = (uint32_t)__cvta_generic_to_shared(&Bs2[0][col][c]);
    }

    const int gr = brow + a_row;

    // ---- prologue: chunk 0 into buf 0 ----
    {
        float4 av = make_float4(0.f, 0.f, 0.f, 0.f);
        if (gr < M)
            av = *reinterpret_cast<const float4*>(&A[(long long)gr * NFEAT + a_kq * 2]);
        uint2 au;
        au.x = pack_h2(av.x, av.y);
        au.y = pack_h2(av.z, av.w);
        *reinterpret_cast<uint2*>(&As2[0][a_row][a_kq]) = au;
        uint2 bu = *reinterpret_cast<const uint2*>(&g_w1p[b_nn * 128 + b_kq]);
        *reinterpret_cast<uint2*>(&Bs2[0][b_nn][b_kq]) = bu;
    }
    __syncthreads();

    #pragma unroll 1
    for (int it = 0; it < 16; it++) {
        const int cur = it & 1;
        const uint32_t boff = cur ? BUFB : 0;

        float4 av;
        uint2  bu;
        const bool more = (it < 15);
        if (more) {
            const int k1 = (it + 1) * 16;
            av = make_float4(0.f, 0.f, 0.f, 0.f);
            if (gr < M)
                av = *reinterpret_cast<const float4*>(&A[(long long)gr * NFEAT + k1 + a_kq * 2]);
            bu = *reinterpret_cast<const uint2*>(&g_w1p[b_nn * 128 + (k1 >> 1) + b_kq]);
        }

        uint32_t afr[2][4], bfr[2][4];
        ldmat4(afr[0], addrA0[0] + boff);
        ldmat4(afr[1], addrA0[1] + boff);
        ldmat4(bfr[0], addrB0[0] + boff);
        ldmat4(bfr[1], addrB0[1] + boff);
        #pragma unroll
        for (int nt = 0; nt < 4; nt++) {
            uint32_t b0 = bfr[nt >> 1][(nt & 1) * 2];
            uint32_t b1 = bfr[nt >> 1][(nt & 1) * 2 + 1];
            mma_f16(acc[0][nt], afr[0], b0, b1);
            mma_f16(acc[1][nt], afr[1], b0, b1);
        }

        if (more) {
            uint2 au;
            au.x = pack_h2(av.x, av.y);
            au.y = pack_h2(av.z, av.w);
            *reinterpret_cast<uint2*>(&As2[cur ^ 1][a_row][a_kq]) = au;
            *reinterpret_cast<uint2*>(&Bs2[cur ^ 1][b_nn][b_kq]) = bu;
            __syncthreads();
        }
    }

    // epilogue: write h1 as fp16
    const int r4 = lane >> 2;
    const int c4 = lane & 3;
    #pragma unroll
    for (int mt = 0; mt < 2; mt++) {
        int row0 = brow + warp_m + mt * 16 + r4;
        #pragma unroll
        for (int nt = 0; nt < 4; nt++) {
            int col = warp_n + nt * 8 + 2 * c4;
            if (row0 < M)
                *reinterpret_cast<__half2*>(&g_h1h[(long long)row0 * NHID + col]) =
                    __floats2half2_rn(acc[mt][nt][0], acc[mt][nt][1]);
            if (row0 + 8 < M)
                *reinterpret_cast<__half2*>(&g_h1h[(long long)(row0 + 8) * NHID + col]) =
                    __floats2half2_rn(acc[mt][nt][2], acc[mt][nt][3]);
        }
    }
}

// ---------------- agg1: g1 = relu(Ahat @ h1 + b1), warp per node, unroll 8 --
__global__ void __launch_bounds__(256, 3) k_agg1(const float* __restrict__ b1, int n) {
    int gtid = blockIdx.x * blockDim.x + threadIdx.x;
    int node = gtid >> 5;
    int lane = threadIdx.x & 31;
    if (node >= n) return;
    const uint2* h1v = reinterpret_cast<const uint2*>(g_h1h); // 8B = 4 halves per lane
    float dv = g_dinv[node];
    float sw = dv * dv;

    uint2 hu = h1v[(long long)node * 32 + lane];
    float2 p0 = __half22float2(*reinterpret_cast<__half2*>(&hu.x));
    float2 p1 = __half22float2(*reinterpret_cast<__half2*>(&hu.y));
    float ax = p0.x * sw, ay = p0.y * sw, az = p1.x * sw, aw = p1.y * sw;

    int p = g_off[node], end = g_off[node + 1];
    for (; p + 7 < end; p += 8) {
        int2 ee[8];
        uint2 uu[8];
        #pragma unroll
        for (int q = 0; q < 8; q++) ee[q] = g_edge[p + q];
        #pragma unroll
        for (int q = 0; q < 8; q++) uu[q] = h1v[(long long)ee[q].x * 32 + lane];
        #pragma unroll
        for (int q = 0; q < 8; q++) {
            float w = __int_as_float(ee[q].y);
            float2 a = __half22float2(*reinterpret_cast<__half2*>(&uu[q].x));
            float2 c = __half22float2(*reinterpret_cast<__half2*>(&uu[q].y));
            ax += a.x * w; ay += a.y * w; az += c.x * w; aw += c.y * w;
        }
    }
    for (; p < end; p++) {
        int2 e0 = g_edge[p];
        float w0 = __int_as_float(e0.y);
        uint2 u0 = h1v[(long long)e0.x * 32 + lane];
        float2 a0 = __half22float2(*reinterpret_cast<__half2*>(&u0.x));
        float2 c0 = __half22float2(*reinterpret_cast<__half2*>(&u0.y));
        ax += a0.x * w0; ay += a0.y * w0; az += c0.x * w0; aw += c0.y * w0;
    }
    float4 bb = reinterpret_cast<const float4*>(b1)[lane];
    uint2 out;
    out.x = pack_h2(fmaxf(ax + bb.x, 0.f), fmaxf(ay + bb.y, 0.f));
    out.y = pack_h2(fmaxf(az + bb.z, 0.f), fmaxf(aw + bb.w, 0.f));
    g_g1h[(long long)node * 32 + lane] = out;
}

// ---------------- GEMM2: h2 = g1(Mx128 fp16) @ W2(128x16), fp16 out ---------
#define GP 68    // s_g row pad (floats)
#define WP 132   // s_wt row pad (floats)
__global__ void __launch_bounds__(128) k_gemm2(const float* __restrict__ W2, int M) {
    __shared__ float s_g[128][GP];   // [node][k-chunk 64] (unpacked fp32)
    __shared__ float s_wt[16][WP];   // [col][k 0..127] transposed W2
    const int tid  = threadIdx.x;
    const int ng   = tid >> 2;       // node group 0..31 (4 nodes each)
    const int cg   = tid & 3;        // col group 0..3 (4 cols each)
    const int node0 = blockIdx.x * 128;

    for (int idx = tid; idx < 2048; idx += 128) {
        int k = idx >> 4, j = idx & 15;
        s_wt[j][k] = W2[idx];
    }

    float acc[4][4];
    #pragma unroll
    for (int m = 0; m < 4; m++)
        #pragma unroll
        for (int j = 0; j < 4; j++) acc[m][j] = 0.f;

    #pragma unroll
    for (int kc = 0; kc < 2; kc++) {
        const int k0 = kc * 64;
        __syncthreads();
        #pragma unroll
        for (int i = 0; i < 16; i++) {
            int idx = i * 128 + tid;
            int nd = idx >> 4, kq = idx & 15;
            float4 v = make_float4(0.f, 0.f, 0.f, 0.f);
            if (node0 + nd < M) {
                uint2 u = g_g1h[(long long)(node0 + nd) * 32 + (k0 >> 2) + kq];
                float2 lo = __half22float2(*reinterpret_cast<__half2*>(&u.x));
                float2 hi = __half22float2(*reinterpret_cast<__half2*>(&u.y));
                v = make_float4(lo.x, lo.y, hi.x, hi.y);
            }
            *reinterpret_cast<float4*>(&s_g[nd][kq * 4]) = v;
        }
        __syncthreads();
        #pragma unroll
        for (int kq = 0; kq < 16; kq++) {
            float4 a[4], b[4];
            #pragma unroll
            for (int m = 0; m < 4; m++)
                a[m] = *reinterpret_cast<const float4*>(&s_g[ng * 4 + m][kq * 4]);
            #pragma unroll
            for (int j = 0; j < 4; j++)
                b[j] = *reinterpret_cast<const float4*>(&s_wt[cg * 4 + j][k0 + kq * 4]);
            #pragma unroll
            for (int m = 0; m < 4; m++)
                #pragma unroll
                for (int j = 0; j < 4; j++)
                    acc[m][j] += a[m].x * b[j].x + a[m].y * b[j].y
                               + a[m].z * b[j].z + a[m].w * b[j].w;
        }
    }

    #pragma unroll
    for (int m = 0; m < 4; m++) {
        int nd = node0 + ng * 4 + m;
        if (nd < M) {
            __half2 q0 = __floats2half2_rn(acc[m][0], acc[m][1]);
            __half2 q1 = __floats2half2_rn(acc[m][2], acc[m][3]);
            *reinterpret_cast<__half2*>(&g_h2h[(long long)nd * 16 + cg * 4])     = q0;
            *reinterpret_cast<__half2*>(&g_h2h[(long long)nd * 16 + cg * 4 + 2]) = q1;
        }
    }
}

// ---------------- agg2: out = Ahat @ h2 + b2, 16 threads per node, fp16 ----
__global__ void __launch_bounds__(256) k_agg2(const float* __restrict__ b2,
                                              float* __restrict__ out, int n) {
    int gtid = blockIdx.x * blockDim.x + threadIdx.x;
    int node = gtid >> 4;
    int lane = threadIdx.x & 15;
    if (node >= n) return;
    float dv = g_dinv[node];
    float acc = __half2float(g_h2h[(long long)node * 16 + lane]) * dv * dv;
    int p = g_off[node], end = g_off[node + 1];
    for (; p + 3 < end; p += 4) {
        int2 e0 = g_edge[p],     e1 = g_edge[p + 1];
        int2 e2 = g_edge[p + 2], e3 = g_edge[p + 3];
        acc += __half2float(g_h2h[(long long)e0.x * 16 + lane]) * __int_as_float(e0.y)
             + __half2float(g_h2h[(long long)e1.x * 16 + lane]) * __int_as_float(e1.y)
             + __half2float(g_h2h[(long long)e2.x * 16 + lane]) * __int_as_float(e2.y)
             + __half2float(g_h2h[(long long)e3.x * 16 + lane]) * __int_as_float(e3.y);
    }
    for (; p < end; p++) {
        int2 e0 = g_edge[p];
        acc += __half2float(g_h2h[(long long)e0.x * 16 + lane]) * __int_as_float(e0.y);
    }
    out[(long long)node * 16 + lane] = acc + b2[lane];
}

// ---------------- launch ----------------------------------------------------
extern "C" void kernel_launch(void* const* d_in, const int* in_sizes, int n_in,
                              void* d_out, int out_size) {
    const float* x  = (const float*)d_in[0];
    const void*  ei = d_in[1];
    const float* W1 = (const float*)d_in[2];
    const float* b1 = (const float*)d_in[3];
    const float* W2 = (const float*)d_in[4];
    const float* b2 = (const float*)d_in[5];
    float* out = (float*)d_out;

    int n = in_sizes[0] / NFEAT;
    int E = in_sizes[1] / 2;

    int gE = (E + 255) / 256;
    int nb = (n + SCANB - 1) / SCANB;

    const bool fork = g_hx.ok;
    cudaStream_t sb = fork ? g_hx.s2 : (cudaStream_t)0;

    // fork: graph-build chain (s2) runs concurrently with W1 convert + GEMM1.
    // k_scan is the 4th host launch so ncu profiles the new fused scan.
    if (fork) {
        cudaEventRecord(g_hx.evA, 0);
        cudaStreamWaitEvent(g_hx.s2, g_hx.evA, 0);
    }
    k_init<<<1, 256, 0, sb>>>((const int*)ei, E);                   // 1
    k_count<<<gE, 256, 0, sb>>>(ei, E);                             // 2
    k_w1h<<<64, 256>>>(W1);                                         // 3 (stream 0)
    k_scan<<<nb, SCANB, 0, sb>>>(n, nb);                            // 4
    k_gemm1<<<(n + 127) / 128, 512>>>(x, n);                        // 5 (stream 0)
    k_scatter<<<gE, 256, 0, sb>>>(ei, E);                           // 6
    if (fork) {
        cudaEventRecord(g_hx.evB, g_hx.s2);
        cudaStreamWaitEvent(0, g_hx.evB, 0);                        // join
    }
    k_agg1<<<(n * 32 + 255) / 256, 256>>>(b1, n);                   // 7
    k_gemm2<<<(n + 127) / 128, 128>>>(W2, n);                       // 8
    k_agg2<<<(n * 16 + 255) / 256, 256>>>(b2, out, n);              // 9
}

// round 16
// speedup vs baseline: 1.0323x; 1.0323x over previous
#include <cuda_runtime.h>
#include <cuda_fp16.h>
#include <cstdint>

#define NFEAT   256
#define NHID    128
#define NCLS    16
#define MAXN    100000
#define MAXE    1600000
#define SCANB   1024
#define MAXBLK  128

// ---------------- scratch (device globals; no allocation allowed) ----------
__device__ int    g_cnt[MAXN];
__device__ int    g_cur[MAXN];
__device__ int    g_off[MAXN + 1];
__device__ int    g_bsum[MAXBLK];
__device__ int    g_done;
__device__ float  g_dinv[MAXN];
__device__ int2   g_edge[MAXE];             // x = src node, y = weight bits
__device__ uint32_t g_w1p[NHID * (NFEAT / 2)]; // W1 fp16, [n][k-pair] packed
__device__ __half g_h1h[(size_t)MAXN * NHID];   // h1 in fp16 (gather-friendly)
__device__ uint2  g_g1h[(size_t)MAXN * 32];     // g1 in fp16 (packed 4/lane)
__device__ __half g_h2h[(size_t)MAXN * NCLS];   // h2 in fp16
__device__ int    g_is64;

// ---------------- static host context: fork-join stream + events -----------
struct HxCtx {
    cudaStream_t s2;
    cudaEvent_t  evA, evB;
    bool ok;
    HxCtx() : ok(false) {
        if (cudaStreamCreateWithFlags(&s2, cudaStreamNonBlocking) != cudaSuccess) return;
        if (cudaEventCreateWithFlags(&evA, cudaEventDisableTiming) != cudaSuccess) return;
        if (cudaEventCreateWithFlags(&evB, cudaEventDisableTiming) != cudaSuccess) return;
        ok = true;
    }
};
static HxCtx g_hx;

// ---------------- index fetch (runtime int32/int64 dispatch) ---------------
__device__ __forceinline__ int edge_idx(const void* ei, long long pos, int is64) {
    if (is64) return (int)((const long long*)ei)[pos];
    return ((const int*)ei)[pos];
}

// ---------------- init: detect index dtype (zeroing lives in k_scan) -------
__global__ void k_init(const int* __restrict__ ei32, int E) {
    int samples = 4096;
    if (samples > E / 2) samples = E / 2;
    int nz = 0;
    for (int s = threadIdx.x; s < samples; s += blockDim.x)
        if (ei32[2 * s + 1] != 0) nz = 1;
    nz = __syncthreads_or(nz);
    if (threadIdx.x == 0) g_is64 = nz ? 0 : 1;
}

// ---------------- degree count (+ reset scan's done counter) ---------------
__global__ void k_count(const void* __restrict__ ei, int E) {
    if (blockIdx.x == 0 && threadIdx.x == 0) g_done = 0;
    int e = blockIdx.x * blockDim.x + threadIdx.x;
    if (e >= E) return;
    int c = edge_idx(ei, (long long)E + e, g_is64);
    atomicAdd(&g_cnt[c], 1);
}

// ---------------- single-pass scan: off/cur/dinv + zero cnt ----------------
// All nb (<=98) blocks are co-resident (one wave on 148 SMs), so the
// publish-then-spin pattern cannot deadlock.
__global__ void __launch_bounds__(SCANB) k_scan(int n, int nb) {
    __shared__ int warp_sums[32];
    __shared__ int s_prefix;
    int tid = threadIdx.x, lane = tid & 31, wid = tid >> 5;
    int b = blockIdx.x;
    int i = b * SCANB + tid;
    int v = (i < n) ? g_cnt[i] : 0;
    if (i < n) {
        g_dinv[i] = rsqrtf((float)v + 1.0f); // +1 = self loop
        g_cnt[i] = 0;                        // re-zero for next replay
    }
    int x = v;
    #pragma unroll
    for (int d = 1; d < 32; d <<= 1) {
        int y = __shfl_up_sync(0xffffffffu, x, d);
        if (lane >= d) x += y;
    }
    if (lane == 31) warp_sums[wid] = x;
    __syncthreads();
    if (wid == 0) {
        int s = warp_sums[lane];
        #pragma unroll
        for (int d = 1; d < 32; d <<= 1) {
            int y = __shfl_up_sync(0xffffffffu, s, d);
            if (lane >= d) s += y;
        }
        warp_sums[lane] = s;
    }
    __syncthreads();
    int excl = x - v + (wid ? warp_sums[wid - 1] : 0);
    int total = warp_sums[31];

    if (tid == 0) {
        g_bsum[b] = total;
        __threadfence();
        atomicAdd(&g_done, 1);
        while (*(volatile int*)&g_done < nb) { }
        __threadfence();
        int pre = 0;
        for (int j = 0; j < b; j++) pre += g_bsum[j];
        s_prefix = pre;
        if (b == nb - 1) g_off[n] = pre + total;
    }
    __syncthreads();
    int off = excl + s_prefix;
    if (i < n) { g_off[i] = off; g_cur[i] = off; }
}

// ---------------- scatter edges into CSC (interleaved src+w) ---------------
__global__ void k_scatter(const void* __restrict__ ei, int E) {
    int e = blockIdx.x * blockDim.x + threadIdx.x;
    if (e >= E) return;
    int is64 = g_is64;
    int r = edge_idx(ei, e, is64);
    int c = edge_idx(ei, (long long)E + e, is64);
    int p = atomicAdd(&g_cur[c], 1);
    g_edge[p] = make_int2(r, __float_as_int(g_dinv[r] * g_dinv[c]));
}

// ---------------- fp16 mma / ldmatrix helpers -------------------------------
__device__ __forceinline__ void mma_f16(float* d, const uint32_t* a, uint32_t b0, uint32_t b1) {
    asm("mma.sync.aligned.m16n8k16.row.col.f32.f16.f16.f32 "
        "{%0,%1,%2,%3}, {%4,%5,%6,%7}, {%8,%9}, {%0,%1,%2,%3};"
        : "+f"(d[0]), "+f"(d[1]), "+f"(d[2]), "+f"(d[3])
        : "r"(a[0]), "r"(a[1]), "r"(a[2]), "r"(a[3]), "r"(b0), "r"(b1));
}
__device__ __forceinline__ void ldmat4(uint32_t* r, uint32_t addr) {
    asm volatile("ldmatrix.sync.aligned.m8n8.x4.shared.b16 {%0,%1,%2,%3}, [%4];"
        : "=r"(r[0]), "=r"(r[1]), "=r"(r[2]), "=r"(r[3]) : "r"(addr));
}
__device__ __forceinline__ uint32_t pack_h2(float lo, float hi) {
    __half2 h = __floats2half2_rn(lo, hi);
    return *reinterpret_cast<uint32_t*>(&h);
}

// ---------------- W1 pre-convert: g_w1p[n][u] = (h(W1[2u][n]), h(W1[2u+1][n]))
__global__ void k_w1h(const float* __restrict__ W1) {
    int idx = blockIdx.x * blockDim.x + threadIdx.x;  // 0..16383
    int nn = idx >> 7, u = idx & 127;
    g_w1p[nn * 128 + u] = pack_h2(W1[(2 * u) * NHID + nn], W1[(2 * u + 1) * NHID + nn]);
}

// ---------------- GEMM1: 512 threads, 16 warps (4x4), warp tile 32x32 -------
#define AP2 12   // padded row length (uints)
#define BUFB (128 * AP2 * 4)   // bytes per buffer
__global__ void __launch_bounds__(512, 2) k_gemm1(const float* __restrict__ A,
                                                  int M) {
    __shared__ uint32_t As2[2][128][AP2];  // A halves: [buf][row][k-pair]
    __shared__ uint32_t Bs2[2][128][AP2];  // B halves: [buf][col][k-pair]
    const int tid    = threadIdx.x;
    const int lane   = tid & 31;
    const int wid    = tid >> 5;          // 0..15
    const int warp_m = (wid & 3) * 32;    // 4 warps along M
    const int warp_n = (wid >> 2) * 32;   // 4 warps along N
    const int brow   = blockIdx.x * 128;

    float acc[2][4][4];
    #pragma unroll
    for (int mt = 0; mt < 2; mt++)
        #pragma unroll
        for (int nt = 0; nt < 4; nt++)
            #pragma unroll
            for (int q = 0; q < 4; q++) acc[mt][nt][q] = 0.f;

    const int a_row = tid >> 2;          // 0..127
    const int a_kq  = (tid & 3) * 2;     // uint index 0,2,4,6
    const int b_nn  = a_row;
    const int b_kq  = a_kq;

    uint32_t addrA0[2], addrB0[2];
    #pragma unroll
    for (int mt = 0; mt < 2; mt++) {
        int row = warp_m + mt * 16 + (lane & 15);
        int c   = (lane >> 4) * 4;
        addrA0[mt] = (uint32_t)__cvta_generic_to_shared(&As2[0][row][c]);
    }
    #pragma unroll
    for (int i = 0; i < 2; i++) {
        int m = lane >> 3, r = lane & 7;
        int col = warp_n + (2 * i + (m >> 1)) * 8 + r;
        int c   = (m & 1) * 4;
        addrB0[i] = (uint32_t)__cvta_generic_to_shared(&Bs2[0][col][c]);
    }

    const int gr = brow + a_row;

    // ---- prologue: chunk 0 into buf 0 ----
    {
        float4 av = make_float4(0.f, 0.f, 0.f, 0.f);
        if (gr < M)
            av = *reinterpret_cast<const float4*>(&A[(long long)gr * NFEAT + a_kq * 2]);
        uint2 au;
        au.x = pack_h2(av.x, av.y);
        au.y = pack_h2(av.z, av.w);
        *reinterpret_cast<uint2*>(&As2[0][a_row][a_kq]) = au;
        uint2 bu = *reinterpret_cast<const uint2*>(&g_w1p[b_nn * 128 + b_kq]);
        *reinterpret_cast<uint2*>(&Bs2[0][b_nn][b_kq]) = bu;
    }
    __syncthreads();

    #pragma unroll 1
    for (int it = 0; it < 16; it++) {
        const int cur = it & 1;
        const uint32_t boff = cur ? BUFB : 0;

        float4 av;
        uint2  bu;
        const bool more = (it < 15);
        if (more) {
            const int k1 = (it + 1) * 16;
            av = make_float4(0.f, 0.f, 0.f, 0.f);
            if (gr < M)
                av = *reinterpret_cast<const float4*>(&A[(long long)gr * NFEAT + k1 + a_kq * 2]);
            bu = *reinterpret_cast<const uint2*>(&g_w1p[b_nn * 128 + (k1 >> 1) + b_kq]);
        }

        uint32_t afr[2][4], bfr[2][4];
        ldmat4(afr[0], addrA0[0] + boff);
        ldmat4(afr[1], addrA0[1] + boff);
        ldmat4(bfr[0], addrB0[0] + boff);
        ldmat4(bfr[1], addrB0[1] + boff);
        #pragma unroll
        for (int nt = 0; nt < 4; nt++) {
            uint32_t b0 = bfr[nt >> 1][(nt & 1) * 2];
            uint32_t b1 = bfr[nt >> 1][(nt & 1) * 2 + 1];
            mma_f16(acc[0][nt], afr[0], b0, b1);
            mma_f16(acc[1][nt], afr[1], b0, b1);
        }

        if (more) {
            uint2 au;
            au.x = pack_h2(av.x, av.y);
            au.y = pack_h2(av.z, av.w);
            *reinterpret_cast<uint2*>(&As2[cur ^ 1][a_row][a_kq]) = au;
            *reinterpret_cast<uint2*>(&Bs2[cur ^ 1][b_nn][b_kq]) = bu;
            __syncthreads();
        }
    }

    // epilogue: write h1 as fp16
    const int r4 = lane >> 2;
    const int c4 = lane & 3;
    #pragma unroll
    for (int mt = 0; mt < 2; mt++) {
        int row0 = brow + warp_m + mt * 16 + r4;
        #pragma unroll
        for (int nt = 0; nt < 4; nt++) {
            int col = warp_n + nt * 8 + 2 * c4;
            if (row0 < M)
                *reinterpret_cast<__half2*>(&g_h1h[(long long)row0 * NHID + col]) =
                    __floats2half2_rn(acc[mt][nt][0], acc[mt][nt][1]);
            if (row0 + 8 < M)
                *reinterpret_cast<__half2*>(&g_h1h[(long long)(row0 + 8) * NHID + col]) =
                    __floats2half2_rn(acc[mt][nt][2], acc[mt][nt][3]);
        }
    }
}

// ---------------- agg1: g1 = relu(Ahat @ h1 + b1), warp per node, unroll 4 --
__global__ void __launch_bounds__(256) k_agg1(const float* __restrict__ b1, int n) {
    int gtid = blockIdx.x * blockDim.x + threadIdx.x;
    int node = gtid >> 5;
    int lane = threadIdx.x & 31;
    if (node >= n) return;
    const uint2* h1v = reinterpret_cast<const uint2*>(g_h1h); // 8B = 4 halves per lane
    float dv = g_dinv[node];
    float sw = dv * dv;

    uint2 hu = h1v[(long long)node * 32 + lane];
    float2 p0 = __half22float2(*reinterpret_cast<__half2*>(&hu.x));
    float2 p1 = __half22float2(*reinterpret_cast<__half2*>(&hu.y));
    float ax = p0.x * sw, ay = p0.y * sw, az = p1.x * sw, aw = p1.y * sw;

    int p = g_off[node], end = g_off[node + 1];
    for (; p + 3 < end; p += 4) {
        int2 e0 = g_edge[p],     e1 = g_edge[p + 1];
        int2 e2 = g_edge[p + 2], e3 = g_edge[p + 3];
        float w0 = __int_as_float(e0.y), w1 = __int_as_float(e1.y);
        float w2 = __int_as_float(e2.y), w3 = __int_as_float(e3.y);
        uint2 u0 = h1v[(long long)e0.x * 32 + lane];
        uint2 u1 = h1v[(long long)e1.x * 32 + lane];
        uint2 u2 = h1v[(long long)e2.x * 32 + lane];
        uint2 u3 = h1v[(long long)e3.x * 32 + lane];
        float2 a0 = __half22float2(*reinterpret_cast<__half2*>(&u0.x));
        float2 c0 = __half22float2(*reinterpret_cast<__half2*>(&u0.y));
        float2 a1 = __half22float2(*reinterpret_cast<__half2*>(&u1.x));
        float2 c1 = __half22float2(*reinterpret_cast<__half2*>(&u1.y));
        float2 a2 = __half22float2(*reinterpret_cast<__half2*>(&u2.x));
        float2 c2 = __half22float2(*reinterpret_cast<__half2*>(&u2.y));
        float2 a3 = __half22float2(*reinterpret_cast<__half2*>(&u3.x));
        float2 c3 = __half22float2(*reinterpret_cast<__half2*>(&u3.y));
        ax += a0.x * w0 + a1.x * w1 + a2.x * w2 + a3.x * w3;
        ay += a0.y * w0 + a1.y * w1 + a2.y * w2 + a3.y * w3;
        az += c0.x * w0 + c1.x * w1 + c2.x * w2 + c3.x * w3;
        aw += c0.y * w0 + c1.y * w1 + c2.y * w2 + c3.y * w3;
    }
    for (; p < end; p++) {
        int2 e0 = g_edge[p];
        float w0 = __int_as_float(e0.y);
        uint2 u0 = h1v[(long long)e0.x * 32 + lane];
        float2 a0 = __half22float2(*reinterpret_cast<__half2*>(&u0.x));
        float2 c0 = __half22float2(*reinterpret_cast<__half2*>(&u0.y));
        ax += a0.x * w0; ay += a0.y * w0; az += c0.x * w0; aw += c0.y * w0;
    }
    float4 bb = reinterpret_cast<const float4*>(b1)[lane];
    uint2 out;
    out.x = pack_h2(fmaxf(ax + bb.x, 0.f), fmaxf(ay + bb.y, 0.f));
    out.y = pack_h2(fmaxf(az + bb.z, 0.f), fmaxf(aw + bb.w, 0.f));
    g_g1h[(long long)node * 32 + lane] = out;
}

// ---------------- GEMM2: h2 = g1(Mx128 fp16) @ W2(128x16), fp16 out ---------
#define GP 68    // s_g row pad (floats)
#define WP 132   // s_wt row pad (floats)
__global__ void __launch_bounds__(128) k_gemm2(const float* __restrict__ W2, int M) {
    __shared__ float s_g[128][GP];   // [node][k-chunk 64] (unpacked fp32)
    __shared__ float s_wt[16][WP];   // [col][k 0..127] transposed W2
    const int tid  = threadIdx.x;
    const int ng   = tid >> 2;       // node group 0..31 (4 nodes each)
    const int cg   = tid & 3;        // col group 0..3 (4 cols each)
    const int node0 = blockIdx.x * 128;

    for (int idx = tid; idx < 2048; idx += 128) {
        int k = idx >> 4, j = idx & 15;
        s_wt[j][k] = W2[idx];
    }

    float acc[4][4];
    #pragma unroll
    for (int m = 0; m < 4; m++)
        #pragma unroll
        for (int j = 0; j < 4; j++) acc[m][j] = 0.f;

    #pragma unroll
    for (int kc = 0; kc < 2; kc++) {
        const int k0 = kc * 64;
        __syncthreads();
        #pragma unroll
        for (int i = 0; i < 16; i++) {
            int idx = i * 128 + tid;
            int nd = idx >> 4, kq = idx & 15;
            float4 v = make_float4(0.f, 0.f, 0.f, 0.f);
            if (node0 + nd < M) {
                uint2 u = g_g1h[(long long)(node0 + nd) * 32 + (k0 >> 2) + kq];
                float2 lo = __half22float2(*reinterpret_cast<__half2*>(&u.x));
                float2 hi = __half22float2(*reinterpret_cast<__half2*>(&u.y));
                v = make_float4(lo.x, lo.y, hi.x, hi.y);
            }
            *reinterpret_cast<float4*>(&s_g[nd][kq * 4]) = v;
        }
        __syncthreads();
        #pragma unroll
        for (int kq = 0; kq < 16; kq++) {
            float4 a[4], b[4];
            #pragma unroll
            for (int m = 0; m < 4; m++)
                a[m] = *reinterpret_cast<const float4*>(&s_g[ng * 4 + m][kq * 4]);
            #pragma unroll
            for (int j = 0; j < 4; j++)
                b[j] = *reinterpret_cast<const float4*>(&s_wt[cg * 4 + j][k0 + kq * 4]);
            #pragma unroll
            for (int m = 0; m < 4; m++)
                #pragma unroll
                for (int j = 0; j < 4; j++)
                    acc[m][j] += a[m].x * b[j].x + a[m].y * b[j].y
                               + a[m].z * b[j].z + a[m].w * b[j].w;
        }
    }

    #pragma unroll
    for (int m = 0; m < 4; m++) {
        int nd = node0 + ng * 4 + m;
        if (nd < M) {
            __half2 q0 = __floats2half2_rn(acc[m][0], acc[m][1]);
            __half2 q1 = __floats2half2_rn(acc[m][2], acc[m][3]);
            *reinterpret_cast<__half2*>(&g_h2h[(long long)nd * 16 + cg * 4])     = q0;
            *reinterpret_cast<__half2*>(&g_h2h[(long long)nd * 16 + cg * 4 + 2]) = q1;
        }
    }
}

// ---------------- agg2: out = Ahat @ h2 + b2, 16 threads per node, fp16 ----
__global__ void __launch_bounds__(256) k_agg2(const float* __restrict__ b2,
                                              float* __restrict__ out, int n) {
    int gtid = blockIdx.x * blockDim.x + threadIdx.x;
    int node = gtid >> 4;
    int lane = threadIdx.x & 15;
    if (node >= n) return;
    float dv = g_dinv[node];
    float acc = __half2float(g_h2h[(long long)node * 16 + lane]) * dv * dv;
    int p = g_off[node], end = g_off[node + 1];
    for (; p + 3 < end; p += 4) {
        int2 e0 = g_edge[p],     e1 = g_edge[p + 1];
        int2 e2 = g_edge[p + 2], e3 = g_edge[p + 3];
        acc += __half2float(g_h2h[(long long)e0.x * 16 + lane]) * __int_as_float(e0.y)
             + __half2float(g_h2h[(long long)e1.x * 16 + lane]) * __int_as_float(e1.y)
             + __half2float(g_h2h[(long long)e2.x * 16 + lane]) * __int_as_float(e2.y)
             + __half2float(g_h2h[(long long)e3.x * 16 + lane]) * __int_as_float(e3.y);
    }
    for (; p < end; p++) {
        int2 e0 = g_edge[p];
        acc += __half2float(g_h2h[(long long)e0.x * 16 + lane]) * __int_as_float(e0.y);
    }
    out[(long long)node * 16 + lane] = acc + b2[lane];
}

// ---------------- launch ----------------------------------------------------
extern "C" void kernel_launch(void* const* d_in, const int* in_sizes, int n_in,
                              void* d_out, int out_size) {
    const float* x  = (const float*)d_in[0];
    const void*  ei = d_in[1];
    const float* W1 = (const float*)d_in[2];
    const float* b1 = (const float*)d_in[3];
    const float* W2 = (const float*)d_in[4];
    const float* b2 = (const float*)d_in[5];
    float* out = (float*)d_out;

    int n = in_sizes[0] / NFEAT;
    int E = in_sizes[1] / 2;

    int gE = (E + 255) / 256;
    int nb = (n + SCANB - 1) / SCANB;

    const bool fork = g_hx.ok;
    cudaStream_t sb = fork ? g_hx.s2 : (cudaStream_t)0;

    // fork: graph-build chain (s2) runs concurrently with W1 convert + GEMM1.
    if (fork) {
        cudaEventRecord(g_hx.evA, 0);
        cudaStreamWaitEvent(g_hx.s2, g_hx.evA, 0);
    }
    k_init<<<1, 256, 0, sb>>>((const int*)ei, E);                   // 1
    k_count<<<gE, 256, 0, sb>>>(ei, E);                             // 2
    k_w1h<<<64, 256>>>(W1);                                         // 3 (stream 0)
    k_scan<<<nb, SCANB, 0, sb>>>(n, nb);                            // 4
    k_gemm1<<<(n + 127) / 128, 512>>>(x, n);                        // 5 (stream 0)
    k_scatter<<<gE, 256, 0, sb>>>(ei, E);                           // 6
    if (fork) {
        cudaEventRecord(g_hx.evB, g_hx.s2);
        cudaStreamWaitEvent(0, g_hx.evB, 0);                        // join
    }
    k_agg1<<<(n * 32 + 255) / 256, 256>>>(b1, n);                   // 7
    k_gemm2<<<(n + 127) / 128, 128>>>(W2, n);                       // 8
    k_agg2<<<(n * 16 + 255) / 256, 256>>>(b2, out, n);              // 9
}